// round 9
// baseline (speedup 1.0000x reference)
#include <cuda_runtime.h>
#include <math.h>

// ---------------- problem constants ----------------
#define T_STEPS 2048
#define BATCH   64
#define DHID    512
#define NPRE    1536          // 3*DHID (r | z | g pre-activations from x)
#define CHUNK   256           // time steps per GEMM+recurrence pair
#define NCHUNK  (T_STEPS / CHUNK)
#define GRID_G  128           // persistent CTAs (all resident, 1/SM)
#define GROUPS  4             // batch-tile groups of 32 CTAs (batch-independent)
#define REC_THREADS 256
#define PART_PITCH 272        // padded row pitch for k-split partials (16B mult)
// wr + wz + wg + hv (each 512x16) + part (32 x PART_PITCH)
#define REC_SMEM_FLOATS (512*16*4 + 32*PART_PITCH)
#define REC_SMEM_BYTES  (REC_SMEM_FLOATS * 4)   // 165888 B

// ---------------- packed fp32 (f32x2) helpers -------------------------------
#define PACK2(d, s) \
    asm("mov.b64 %0, {%1, %1};" : "=l"(d) : "r"(__float_as_uint(s)))
#define UNPACK2(lo, hi, s) do {                                       \
    unsigned _ulo, _uhi;                                              \
    asm("mov.b64 {%0, %1}, %2;" : "=r"(_ulo), "=r"(_uhi) : "l"(s));   \
    lo = __uint_as_float(_ulo); hi = __uint_as_float(_uhi); } while (0)
#define FMA2(acc, a, b) \
    asm("fma.rn.f32x2 %0, %1, %2, %0;" : "+l"(acc) : "l"(a), "l"(b))
#define LDS_V2U64(a, b, addr) \
    asm volatile("ld.shared.v2.u64 {%0, %1}, [%2];" \
                 : "=l"(a), "=l"(b) : "r"(addr))

// ---------------- device scratch (allocation-free rule: __device__ globals) ---
__device__ float g_xpre[(size_t)CHUNK * BATCH * NPRE];    // 100.7 MB
__device__ float g_h_tr[2][DHID * BATCH];                 // ping-pong h, [j][b]
__device__ float g_rh_tr[DHID * BATCH];                   // r*h exchange, [j][b]
__device__ volatile unsigned g_flags[GRID_G];             // per-CTA epoch (zero-init)
__device__ unsigned g_cnt_exit[GROUPS];                   // zero-init

__device__ __forceinline__ float fast_sigmoid(float x) {
    return 1.0f / (1.0f + __expf(-x));
}
__device__ __forceinline__ float fast_tanh(float x) {
    return 2.0f / (1.0f + __expf(-2.0f * x)) - 1.0f;
}

// ---- flag barrier: arrive = plain volatile store (no atomics) ---------------
__device__ __forceinline__ void flag_arrive(int cta, unsigned val) {
    __threadfence();                 // publish this CTA's global writes
    g_flags[cta] = val;
}
__device__ __forceinline__ void flag_wait(int grp, unsigned target) {
    if (threadIdx.x < 32) {
        const int peer = grp * 32 + (int)threadIdx.x;
        for (;;) {
            unsigned v = g_flags[peer];
            if (__all_sync(0xffffffffu, v >= target)) break;
        }
    }
    __syncthreads();
}

// =============================================================================
// Kernel 0: zero h0
// =============================================================================
__global__ void init_h_kernel() {
    g_h_tr[0][blockIdx.x * 256 + threadIdx.x] = 0.f;
}

// =============================================================================
// Kernel 1: one chunk of Xpre = [x@Wr_x^T+br | x@Wz_x^T+bz | x@Wg_x^T+bg]
// M = CHUNK*B = 16384, N = 1536, K = 512. 128x128x8 tiles, 8x8 microtile.
// FFMA2: B operand loaded as f32x2 pairs, A duplicated via mov.b64 packs.
// =============================================================================
__global__ void __launch_bounds__(256, 2)
gemm_xpre_kernel(const float* __restrict__ X,
                 const float* __restrict__ Wr, const float* __restrict__ Wz,
                 const float* __restrict__ Wg,
                 const float* __restrict__ br, const float* __restrict__ bz,
                 const float* __restrict__ bg)
{
    __shared__ __align__(16) float As[2][8][128];
    __shared__ __align__(16) float Bs[2][8][128];

    const int tid = threadIdx.x;
    const int nt  = blockIdx.x;          // 0..11
    const int mt  = blockIdx.y;          // 0..127
    const int m0  = mt * 128;
    const int n0  = nt * 128;

    const float* W; const float* bias;
    if (n0 < 512)       { W = Wr; bias = br; }
    else if (n0 < 1024) { W = Wz; bias = bz; }
    else                { W = Wg; bias = bg; }
    const int nb0 = n0 & 511;

    const int lrow = tid >> 1;           // 0..127
    const int lk4  = (tid & 1) * 4;      // 0 or 4

    const float* Aptr = X + (size_t)(m0 + lrow) * 512 + lk4;
    const float* Bptr = W + (size_t)(nb0 + lrow) * 1024 + lk4;

    float4 pa = *(const float4*)Aptr;
    float4 pb = *(const float4*)Bptr;
    As[0][lk4+0][lrow] = pa.x; As[0][lk4+1][lrow] = pa.y;
    As[0][lk4+2][lrow] = pa.z; As[0][lk4+3][lrow] = pa.w;
    Bs[0][lk4+0][lrow] = pb.x; Bs[0][lk4+1][lrow] = pb.y;
    Bs[0][lk4+2][lrow] = pb.z; Bs[0][lk4+3][lrow] = pb.w;
    __syncthreads();

    // acc2[i][jp]: row i (8), column-pair jp (4) -> 8x8 fp32 outputs
    unsigned long long acc2[8][4];
    #pragma unroll
    for (int i = 0; i < 8; ++i)
        #pragma unroll
        for (int j = 0; j < 4; ++j) acc2[i][j] = 0ull;

    const int ty = tid >> 4;
    const int tx = tid & 15;

    const unsigned bs_base = (unsigned)__cvta_generic_to_shared(&Bs[0][0][0]);

    int buf = 0;
    for (int kt = 0; kt < 64; ++kt) {
        if (kt < 63) {
            pa = *(const float4*)(Aptr + (kt + 1) * 8);
            pb = *(const float4*)(Bptr + (kt + 1) * 8);
        }
        #pragma unroll
        for (int kk = 0; kk < 8; ++kk) {
            float ar[8];
            *(float4*)&ar[0] = *(const float4*)&As[buf][kk][ty * 4];
            *(float4*)&ar[4] = *(const float4*)&As[buf][kk][64 + ty * 4];
            unsigned long long bcp[4];
            unsigned baddr = bs_base +
                (unsigned)(((buf * 8 + kk) * 128 + tx * 4) * 4);
            LDS_V2U64(bcp[0], bcp[1], baddr);
            LDS_V2U64(bcp[2], bcp[3], baddr + 64 * 4);
            #pragma unroll
            for (int i = 0; i < 8; ++i) {
                unsigned long long ad;
                PACK2(ad, ar[i]);
                FMA2(acc2[i][0], ad, bcp[0]);
                FMA2(acc2[i][1], ad, bcp[1]);
                FMA2(acc2[i][2], ad, bcp[2]);
                FMA2(acc2[i][3], ad, bcp[3]);
            }
        }
        if (kt < 63) {
            int nb = buf ^ 1;
            As[nb][lk4+0][lrow] = pa.x; As[nb][lk4+1][lrow] = pa.y;
            As[nb][lk4+2][lrow] = pa.z; As[nb][lk4+3][lrow] = pa.w;
            Bs[nb][lk4+0][lrow] = pb.x; Bs[nb][lk4+1][lrow] = pb.y;
            Bs[nb][lk4+2][lrow] = pb.z; Bs[nb][lk4+3][lrow] = pb.w;
        }
        __syncthreads();
        buf ^= 1;
    }

    float bv[8];
    #pragma unroll
    for (int j = 0; j < 8; ++j) {
        int cj = (j < 4) ? (tx * 4 + j) : (64 + tx * 4 + (j - 4));
        bv[j] = bias[nb0 + cj];
    }
    #pragma unroll
    for (int i = 0; i < 8; ++i) {
        int ri = (i < 4) ? (ty * 4 + i) : (64 + ty * 4 + (i - 4));
        float* crow = g_xpre + (size_t)(m0 + ri) * NPRE + n0;
        float a0,a1,a2,a3,a4,a5,a6,a7;
        UNPACK2(a0, a1, acc2[i][0]);
        UNPACK2(a2, a3, acc2[i][1]);
        UNPACK2(a4, a5, acc2[i][2]);
        UNPACK2(a6, a7, acc2[i][3]);
        float4 v0 = make_float4(a0+bv[0], a1+bv[1], a2+bv[2], a3+bv[3]);
        float4 v1 = make_float4(a4+bv[4], a5+bv[5], a6+bv[6], a7+bv[7]);
        *(float4*)(crow + tx * 4)      = v0;
        *(float4*)(crow + 64 + tx * 4) = v1;
    }
}

// =============================================================================
// Kernel 2: persistent recurrence, one CHUNK of steps.
// CTA owns batches [b0,b0+16) x cols [c0,c0+16); group = 32 CTAs sharing b0.
// Gates via FFMA2: thread tile 4b x 8c (4 c-pairs), k-split 32 (16 k each).
// Flags encode epoch: rh arrive = 2*lt+1, h arrive = 2*lt+2.
// =============================================================================
#define GATE_DOTS2(WBASE)                                                      \
    {                                                                          \
        const int bg = tid & 3, cgx = (tid >> 2) & 1, ks = tid >> 3;           \
        unsigned long long a2[4][4];                                           \
        _Pragma("unroll")                                                      \
        for (int i = 0; i < 4; ++i)                                            \
            _Pragma("unroll")                                                  \
            for (int p = 0; p < 4; ++p) a2[i][p] = 0ull;                       \
        const int kb = ks * 16;                                                \
        _Pragma("unroll 4")                                                    \
        for (int k = kb; k < kb + 16; ++k) {                                   \
            float4 h4 = hv4[k * 4 + bg];                                       \
            unsigned long long w0, w1, w2, w3;                                 \
            unsigned waddr = (WBASE) + (unsigned)((k * 16 + cgx * 8) * 4);     \
            LDS_V2U64(w0, w1, waddr);                                          \
            LDS_V2U64(w2, w3, waddr + 16);                                     \
            unsigned long long hd;                                             \
            PACK2(hd, h4.x);                                                   \
            FMA2(a2[0][0], hd, w0); FMA2(a2[0][1], hd, w1);                    \
            FMA2(a2[0][2], hd, w2); FMA2(a2[0][3], hd, w3);                    \
            PACK2(hd, h4.y);                                                   \
            FMA2(a2[1][0], hd, w0); FMA2(a2[1][1], hd, w1);                    \
            FMA2(a2[1][2], hd, w2); FMA2(a2[1][3], hd, w3);                    \
            PACK2(hd, h4.z);                                                   \
            FMA2(a2[2][0], hd, w0); FMA2(a2[2][1], hd, w1);                    \
            FMA2(a2[2][2], hd, w2); FMA2(a2[2][3], hd, w3);                    \
            PACK2(hd, h4.w);                                                   \
            FMA2(a2[3][0], hd, w0); FMA2(a2[3][1], hd, w1);                    \
            FMA2(a2[3][2], hd, w2); FMA2(a2[3][3], hd, w3);                    \
        }                                                                      \
        _Pragma("unroll")                                                      \
        for (int i = 0; i < 4; ++i) {                                          \
            float v0,v1,v2,v3,v4,v5,v6,v7;                                     \
            UNPACK2(v0, v1, a2[i][0]); UNPACK2(v2, v3, a2[i][1]);              \
            UNPACK2(v4, v5, a2[i][2]); UNPACK2(v6, v7, a2[i][3]);              \
            float* dst = &part[ks * PART_PITCH + (bg * 4 + i) * 16 + cgx * 8]; \
            *(float4*)dst       = make_float4(v0, v1, v2, v3);                 \
            *(float4*)(dst + 4) = make_float4(v4, v5, v6, v7);                 \
        }                                                                      \
    }

#define REDUCE32(dst)                                                          \
    {                                                                          \
        float s = 0.f;                                                         \
        _Pragma("unroll")                                                      \
        for (int p = 0; p < 32; ++p) s += part[p * PART_PITCH + tid];          \
        dst = s;                                                               \
    }

// stage [j][b]-major global buffer into hv[k=j][16 b]: float4 both sides
#define STAGE_TR(SRC)                                                          \
    {                                                                          \
        _Pragma("unroll")                                                      \
        for (int q = 0; q < 8; ++q) {                                          \
            const int jrow = jj * 8 + q;                                       \
            float4 v = __ldcg((const float4*)(SRC + jrow * 64 + b0) + q4);     \
            *(float4*)&hv[jrow * 16 + q4 * 4] = v;                             \
        }                                                                      \
    }

__global__ void __launch_bounds__(REC_THREADS, 1)
gru_rec_kernel(const float* __restrict__ Wr, const float* __restrict__ Wz,
               const float* __restrict__ Wg, float* __restrict__ out,
               int mode, int t0)
{
    extern __shared__ __align__(16) float sm[];
    float* wr   = sm;                    // [512 k][16 c]
    float* wz   = wr + 512 * 16;         // [512 k][16 c]
    float* wg   = wz + 512 * 16;         // [512 k][16 c]
    float* hv   = wg + 512 * 16;         // [512 k][16 b] staged h / r*h
    float* part = hv + 512 * 16;         // [32][PART_PITCH] k-split partials

    const int tid = threadIdx.x;
    const int cta = blockIdx.x;
    const int grp = cta >> 5;            // batch-tile group (0..3)
    const int c0  = (cta & 31) * 16;     // 32 col tiles
    const int b0  = grp * 16;            // batch tile

    // ---- preload recurrent weights (h-part cols of W: [512..1024)) ----
    for (int i = tid; i < 512 * 16; i += REC_THREADS) {
        int k = i >> 4, cc2 = i & 15;
        size_t off = (size_t)(c0 + cc2) * 1024 + 512 + k;
        wr[i] = Wr[off];
        wz[i] = Wz[off];
        wg[i] = Wg[off];
    }
    __syncthreads();

    const float4* hv4 = (const float4*)hv;
    const unsigned wr_u = (unsigned)__cvta_generic_to_shared(wr);
    const unsigned wz_u = (unsigned)__cvta_generic_to_shared(wz);
    const unsigned wg_u = (unsigned)__cvta_generic_to_shared(wg);

    // per-thread output coords
    const int bb = tid >> 4, cc = tid & 15;
    const int b  = b0 + bb,  j  = c0 + cc;
    // staging coords
    const int q4 = tid & 3, jj = tid >> 2;   // jj: 0..63, q4: b-quad

    for (int lt = 0; lt < CHUNK; ++lt) {
        const int t   = t0 + lt;
        const int cur = lt & 1;

        // ---- prefetch x-preactivations (off critical path) ----
        const size_t xb = (size_t)(lt * 64 + b) * NPRE + j;
        float xr = __ldcg(&g_xpre[xb]);
        float xz = __ldcg(&g_xpre[xb + 512]);
        float xg = __ldcg(&g_xpre[xb + 1024]);

        // ---- wait for previous step's h_new (own group only) ----
        if (lt > 0) flag_wait(grp, (unsigned)(2 * lt));

        // ---- stage h into hv[k][b] ----
        STAGE_TR(g_h_tr[cur])
        __syncthreads();

        // ---- r gate ----
        GATE_DOTS2(wr_u)
        __syncthreads();
        float rsum; REDUCE32(rsum)
        float hval = hv[j * 16 + bb];                 // h_prev at owned (b,j)
        float rv   = fast_sigmoid(rsum + xr);
        g_rh_tr[j * 64 + b] = rv * hval;
        __syncthreads();                              // rh stores + part reads done
        if (tid == 0) flag_arrive(cta, (unsigned)(2 * lt + 1));

        // ---- z gate (fills barrier window) ----
        GATE_DOTS2(wz_u)
        __syncthreads();
        float zsum; REDUCE32(zsum)
        float zv = fast_sigmoid(zsum + xz);

        // ---- wait for group's r*h, stage into hv ----
        flag_wait(grp, (unsigned)(2 * lt + 1));
        STAGE_TR(g_rh_tr)
        __syncthreads();

        // ---- g gate ----
        GATE_DOTS2(wg_u)
        __syncthreads();
        float gsum; REDUCE32(gsum)
        float gv = fast_tanh(gsum + xg);
        float hn = zv * hval + (1.f - zv) * gv;
        g_h_tr[cur ^ 1][j * 64 + b] = hn;
        if (mode >= 1) out[(size_t)(t * 64 + b) * 512 + j] = hn;
        if (t == T_STEPS - 1) {
            if (mode == 2)
                out[(size_t)T_STEPS * BATCH * DHID + (size_t)b * 512 + j] = hn;
            else if (mode == 0)
                out[(size_t)b * 512 + j] = hn;
        }
        __syncthreads();
        if (tid == 0) flag_arrive(cta, (unsigned)(2 * lt + 2));
    }

    // ---- exit: last CTA of each group resets the group's flags ----
    __syncthreads();
    if (tid == 0) {
        unsigned a = atomicAdd(&g_cnt_exit[grp], 1u);
        if (a == 31) {
            g_cnt_exit[grp] = 0;
            for (int i = 0; i < 32; ++i) g_flags[grp * 32 + i] = 0;
            __threadfence();
        }
    }
}

// =============================================================================
extern "C" void kernel_launch(void* const* d_in, const int* in_sizes, int n_in,
                              void* d_out, int out_size) {
    const float* x  = (const float*)d_in[0];
    const float* Wr = (const float*)d_in[1];
    const float* br = (const float*)d_in[2];
    const float* Wz = (const float*)d_in[3];
    const float* bz = (const float*)d_in[4];
    const float* Wg = (const float*)d_in[5];
    const float* bg = (const float*)d_in[6];
    float* out = (float*)d_out;

    const long long TBH = (long long)T_STEPS * BATCH * DHID;   // 67,108,864
    int mode;
    if ((long long)out_size >= TBH + (long long)BATCH * DHID) mode = 2; // outs + h_final
    else if ((long long)out_size >= TBH)                      mode = 1; // outs only
    else                                                      mode = 0; // h_final only

    cudaFuncSetAttribute(gru_rec_kernel,
                         cudaFuncAttributeMaxDynamicSharedMemorySize,
                         REC_SMEM_BYTES);

    init_h_kernel<<<DHID * BATCH / 256, 256>>>();

    dim3 g1(12, CHUNK * BATCH / 128);    // 12 N-tiles x 128 M-tiles
    for (int c = 0; c < NCHUNK; ++c) {
        const float* xc = x + (size_t)c * CHUNK * BATCH * 512;
        gemm_xpre_kernel<<<g1, 256>>>(xc, Wr, Wz, Wg, br, bz, bg);
        gru_rec_kernel<<<GRID_G, REC_THREADS, REC_SMEM_BYTES>>>(
            Wr, Wz, Wg, out, mode, c * CHUNK);
    }
}

// round 12
// speedup vs baseline: 1.0287x; 1.0287x over previous
#include <cuda_runtime.h>
#include <math.h>

// ---------------- problem constants ----------------
#define T_STEPS 2048
#define BATCH   64
#define DHID    512
#define NPRE    1536          // 3*DHID (r | z | g pre-activations from x)
#define CHUNK   128           // time steps per GEMM+recurrence pair
#define NCHUNK  (T_STEPS / CHUNK)   // 16
#define GRID_G  128           // persistent CTAs (all resident, 1/SM)
#define GROUPS  4             // batch-tile groups of 32 CTAs (batch-independent)
#define REC_THREADS 256
// wr + wz + wg + hv (each 512x16) + part (16x256)
#define REC_SMEM_FLOATS (512*16*4 + 4096)
#define REC_SMEM_BYTES  (REC_SMEM_FLOATS * 4)   // 147456 B

// ---------------- packed fp32 (f32x2) helpers (GEMM only) --------------------
#define PACK2(d, s) \
    asm("mov.b64 %0, {%1, %1};" : "=l"(d) : "r"(__float_as_uint(s)))
#define UNPACK2(lo, hi, s) do {                                       \
    unsigned _ulo, _uhi;                                              \
    asm("mov.b64 {%0, %1}, %2;" : "=r"(_ulo), "=r"(_uhi) : "l"(s));   \
    lo = __uint_as_float(_ulo); hi = __uint_as_float(_uhi); } while (0)
#define FMA2(acc, a, b) \
    asm("fma.rn.f32x2 %0, %1, %2, %0;" : "+l"(acc) : "l"(a), "l"(b))
#define LDS_V2U64(a, b, addr) \
    asm volatile("ld.shared.v2.u64 {%0, %1}, [%2];" \
                 : "=l"(a), "=l"(b) : "r"(addr))

// ---------------- device scratch (allocation-free rule: __device__ globals) ---
// Double-buffered chunk of x-preactivations: 2 x 50.3 MB = 100.7 MB total.
__device__ float g_xpre[2][(size_t)CHUNK * BATCH * NPRE];
__device__ float g_h_tr[2][DHID * BATCH];                 // ping-pong h, [j][b]
__device__ float g_rh_tr[DHID * BATCH];                   // r*h exchange, [j][b]
__device__ volatile unsigned g_flags[GRID_G];             // per-CTA epoch (zero-init)
__device__ unsigned g_cnt_exit[GROUPS];                   // zero-init

__device__ __forceinline__ float fast_sigmoid(float x) {
    return 1.0f / (1.0f + __expf(-x));
}
__device__ __forceinline__ float fast_tanh(float x) {
    return 2.0f / (1.0f + __expf(-2.0f * x)) - 1.0f;
}

// ---- flag barrier: arrive = plain volatile store (no atomics) ---------------
__device__ __forceinline__ void flag_arrive(int cta, unsigned val) {
    __threadfence();                 // publish this CTA's global writes
    g_flags[cta] = val;
}
__device__ __forceinline__ void flag_wait(int grp, unsigned target) {
    if (threadIdx.x < 32) {
        const int peer = grp * 32 + (int)threadIdx.x;
        for (;;) {
            unsigned v = g_flags[peer];
            if (__all_sync(0xffffffffu, v >= target)) break;
        }
    }
    __syncthreads();
}

// =============================================================================
// Kernel 0: zero h0
// =============================================================================
__global__ void init_h_kernel() {
    g_h_tr[0][blockIdx.x * 256 + threadIdx.x] = 0.f;
}

// =============================================================================
// Kernel 1: one chunk of Xpre = [x@Wr_x^T+br | x@Wz_x^T+bz | x@Wg_x^T+bg]
// M = CHUNK*B = 8192, N = 1536, K = 512. 128x128x8 tiles, 8x8 microtile.
// FFMA2 inner product (issue-bound kernel -> packed math wins: 545 -> 490us/2).
// =============================================================================
__global__ void __launch_bounds__(256, 2)
gemm_xpre_kernel(const float* __restrict__ X,
                 const float* __restrict__ Wr, const float* __restrict__ Wz,
                 const float* __restrict__ Wg,
                 const float* __restrict__ br, const float* __restrict__ bz,
                 const float* __restrict__ bg, int buf)
{
    __shared__ __align__(16) float As[2][8][128];
    __shared__ __align__(16) float Bs[2][8][128];

    const int tid = threadIdx.x;
    const int nt  = blockIdx.x;          // 0..11
    const int mt  = blockIdx.y;          // 0..63
    const int m0  = mt * 128;
    const int n0  = nt * 128;

    const float* W; const float* bias;
    if (n0 < 512)       { W = Wr; bias = br; }
    else if (n0 < 1024) { W = Wz; bias = bz; }
    else                { W = Wg; bias = bg; }
    const int nb0 = n0 & 511;

    const int lrow = tid >> 1;           // 0..127
    const int lk4  = (tid & 1) * 4;      // 0 or 4

    const float* Aptr = X + (size_t)(m0 + lrow) * 512 + lk4;
    const float* Bptr = W + (size_t)(nb0 + lrow) * 1024 + lk4;

    float4 pa = *(const float4*)Aptr;
    float4 pb = *(const float4*)Bptr;
    As[0][lk4+0][lrow] = pa.x; As[0][lk4+1][lrow] = pa.y;
    As[0][lk4+2][lrow] = pa.z; As[0][lk4+3][lrow] = pa.w;
    Bs[0][lk4+0][lrow] = pb.x; Bs[0][lk4+1][lrow] = pb.y;
    Bs[0][lk4+2][lrow] = pb.z; Bs[0][lk4+3][lrow] = pb.w;
    __syncthreads();

    unsigned long long acc2[8][4];
    #pragma unroll
    for (int i = 0; i < 8; ++i)
        #pragma unroll
        for (int j = 0; j < 4; ++j) acc2[i][j] = 0ull;

    const int ty = tid >> 4;
    const int tx = tid & 15;

    const unsigned bs_base = (unsigned)__cvta_generic_to_shared(&Bs[0][0][0]);

    int bufl = 0;
    for (int kt = 0; kt < 64; ++kt) {
        if (kt < 63) {
            pa = *(const float4*)(Aptr + (kt + 1) * 8);
            pb = *(const float4*)(Bptr + (kt + 1) * 8);
        }
        #pragma unroll
        for (int kk = 0; kk < 8; ++kk) {
            float ar[8];
            *(float4*)&ar[0] = *(const float4*)&As[bufl][kk][ty * 4];
            *(float4*)&ar[4] = *(const float4*)&As[bufl][kk][64 + ty * 4];
            unsigned long long bcp[4];
            unsigned baddr = bs_base +
                (unsigned)(((bufl * 8 + kk) * 128 + tx * 4) * 4);
            LDS_V2U64(bcp[0], bcp[1], baddr);
            LDS_V2U64(bcp[2], bcp[3], baddr + 64 * 4);
            #pragma unroll
            for (int i = 0; i < 8; ++i) {
                unsigned long long ad;
                PACK2(ad, ar[i]);
                FMA2(acc2[i][0], ad, bcp[0]);
                FMA2(acc2[i][1], ad, bcp[1]);
                FMA2(acc2[i][2], ad, bcp[2]);
                FMA2(acc2[i][3], ad, bcp[3]);
            }
        }
        if (kt < 63) {
            int nb = bufl ^ 1;
            As[nb][lk4+0][lrow] = pa.x; As[nb][lk4+1][lrow] = pa.y;
            As[nb][lk4+2][lrow] = pa.z; As[nb][lk4+3][lrow] = pa.w;
            Bs[nb][lk4+0][lrow] = pb.x; Bs[nb][lk4+1][lrow] = pb.y;
            Bs[nb][lk4+2][lrow] = pb.z; Bs[nb][lk4+3][lrow] = pb.w;
        }
        __syncthreads();
        bufl ^= 1;
    }

    float bv[8];
    #pragma unroll
    for (int j = 0; j < 8; ++j) {
        int cj = (j < 4) ? (tx * 4 + j) : (64 + tx * 4 + (j - 4));
        bv[j] = bias[nb0 + cj];
    }
    float* xout = g_xpre[buf];
    #pragma unroll
    for (int i = 0; i < 8; ++i) {
        int ri = (i < 4) ? (ty * 4 + i) : (64 + ty * 4 + (i - 4));
        float* crow = xout + (size_t)(m0 + ri) * NPRE + n0;
        float a0,a1,a2,a3,a4,a5,a6,a7;
        UNPACK2(a0, a1, acc2[i][0]);
        UNPACK2(a2, a3, acc2[i][1]);
        UNPACK2(a4, a5, acc2[i][2]);
        UNPACK2(a6, a7, acc2[i][3]);
        float4 v0 = make_float4(a0+bv[0], a1+bv[1], a2+bv[2], a3+bv[3]);
        float4 v1 = make_float4(a4+bv[4], a5+bv[5], a6+bv[6], a7+bv[7]);
        *(float4*)(crow + tx * 4)      = v0;
        *(float4*)(crow + 64 + tx * 4) = v1;
    }
}

// =============================================================================
// Kernel 2: persistent recurrence, one CHUNK of steps (R8 scalar-FFMA gates —
// this kernel is latency-bound; packed math regressed it in R9).
// CTA owns batches [b0,b0+16) x cols [c0,c0+16); group = 32 CTAs sharing b0.
// =============================================================================
#define FMA44(acc, h4, w4)                                                     \
    acc[0][0] += h4.x * w4.x; acc[0][1] += h4.x * w4.y;                        \
    acc[0][2] += h4.x * w4.z; acc[0][3] += h4.x * w4.w;                        \
    acc[1][0] += h4.y * w4.x; acc[1][1] += h4.y * w4.y;                        \
    acc[1][2] += h4.y * w4.z; acc[1][3] += h4.y * w4.w;                        \
    acc[2][0] += h4.z * w4.x; acc[2][1] += h4.z * w4.y;                        \
    acc[2][2] += h4.z * w4.z; acc[2][3] += h4.z * w4.w;                        \
    acc[3][0] += h4.w * w4.x; acc[3][1] += h4.w * w4.y;                        \
    acc[3][2] += h4.w * w4.z; acc[3][3] += h4.w * w4.w;

#define GATE_DOTS(Wsm4)                                                        \
    {                                                                          \
        const int bg = tid & 3, cg = (tid >> 2) & 3, ks = tid >> 4;            \
        float acc[4][4] = {};                                                  \
        const int kb = ks * 32;                                                \
        _Pragma("unroll 4")                                                    \
        for (int k = kb; k < kb + 32; ++k) {                                   \
            float4 h4 = hv4[k * 4 + bg];                                       \
            float4 w4 = Wsm4[k * 4 + cg];                                      \
            FMA44(acc, h4, w4)                                                 \
        }                                                                      \
        _Pragma("unroll")                                                      \
        for (int i = 0; i < 4; ++i)                                            \
            *(float4*)&part[ks * 256 + (bg * 4 + i) * 16 + cg * 4] =           \
                make_float4(acc[i][0], acc[i][1], acc[i][2], acc[i][3]);       \
    }

#define REDUCE16(dst)                                                          \
    {                                                                          \
        float s = 0.f;                                                         \
        _Pragma("unroll")                                                      \
        for (int p = 0; p < 16; ++p) s += part[p * 256 + tid];                 \
        dst = s;                                                               \
    }

// stage [j][b]-major global buffer into hv[k=j][16 b]: float4 both sides
#define STAGE_TR(SRC)                                                          \
    {                                                                          \
        _Pragma("unroll")                                                      \
        for (int q = 0; q < 8; ++q) {                                          \
            const int jrow = jj * 8 + q;                                       \
            float4 v = __ldcg((const float4*)(SRC + jrow * 64 + b0) + q4);     \
            *(float4*)&hv[jrow * 16 + q4 * 4] = v;                             \
        }                                                                      \
    }

__global__ void __launch_bounds__(REC_THREADS, 1)
gru_rec_kernel(const float* __restrict__ Wr, const float* __restrict__ Wz,
               const float* __restrict__ Wg, float* __restrict__ out,
               int mode, int t0, int buf)
{
    extern __shared__ __align__(16) float sm[];
    float* wr   = sm;                    // [512 k][16 c]
    float* wz   = wr + 512 * 16;         // [512 k][16 c]
    float* wg   = wz + 512 * 16;         // [512 k][16 c]
    float* hv   = wg + 512 * 16;         // [512 k][16 b] staged h / r*h
    float* part = hv + 512 * 16;         // [16][256] k-split partials

    const int tid = threadIdx.x;
    const int cta = blockIdx.x;
    const int grp = cta >> 5;            // batch-tile group (0..3)
    const int c0  = (cta & 31) * 16;     // 32 col tiles
    const int b0  = grp * 16;            // batch tile

    const float* xpre = g_xpre[buf];

    // ---- preload recurrent weights (h-part cols of W: [512..1024)) ----
    for (int i = tid; i < 512 * 16; i += REC_THREADS) {
        int k = i >> 4, cc2 = i & 15;
        size_t off = (size_t)(c0 + cc2) * 1024 + 512 + k;
        wr[i] = Wr[off];
        wz[i] = Wz[off];
        wg[i] = Wg[off];
    }
    __syncthreads();

    const float4* hv4 = (const float4*)hv;
    const float4* wr4 = (const float4*)wr;
    const float4* wz4 = (const float4*)wz;
    const float4* wg4 = (const float4*)wg;

    // per-thread output coords
    const int bb = tid >> 4, cc = tid & 15;
    const int b  = b0 + bb,  j  = c0 + cc;
    // staging coords
    const int q4 = tid & 3, jj = tid >> 2;   // jj: 0..63, q4: b-quad

    for (int lt = 0; lt < CHUNK; ++lt) {
        const int t   = t0 + lt;
        const int cur = lt & 1;

        // ---- prefetch x-preactivations (off critical path) ----
        const size_t xb = (size_t)(lt * 64 + b) * NPRE + j;
        float xr = __ldcg(&xpre[xb]);
        float xz = __ldcg(&xpre[xb + 512]);
        float xg = __ldcg(&xpre[xb + 1024]);

        // ---- wait for previous step's h_new (own group only) ----
        if (lt > 0) flag_wait(grp, (unsigned)(2 * lt));

        // ---- stage h into hv[k][b] ----
        STAGE_TR(g_h_tr[cur])
        __syncthreads();

        // ---- r gate ----
        GATE_DOTS(wr4)
        __syncthreads();
        float rsum; REDUCE16(rsum)
        float hval = hv[j * 16 + bb];                 // h_prev at owned (b,j)
        float rv   = fast_sigmoid(rsum + xr);
        g_rh_tr[j * 64 + b] = rv * hval;
        __syncthreads();                              // rh stores + part reads done
        if (tid == 0) flag_arrive(cta, (unsigned)(2 * lt + 1));

        // ---- z gate (fills barrier window) ----
        GATE_DOTS(wz4)
        __syncthreads();
        float zsum; REDUCE16(zsum)
        float zv = fast_sigmoid(zsum + xz);

        // ---- wait for group's r*h, stage into hv ----
        flag_wait(grp, (unsigned)(2 * lt + 1));
        STAGE_TR(g_rh_tr)
        __syncthreads();

        // ---- g gate ----
        GATE_DOTS(wg4)
        __syncthreads();
        float gsum; REDUCE16(gsum)
        float gv = fast_tanh(gsum + xg);
        float hn = zv * hval + (1.f - zv) * gv;
        g_h_tr[cur ^ 1][j * 64 + b] = hn;
        if (mode >= 1) out[(size_t)(t * 64 + b) * 512 + j] = hn;
        if (t == T_STEPS - 1) {
            if (mode == 2)
                out[(size_t)T_STEPS * BATCH * DHID + (size_t)b * 512 + j] = hn;
            else if (mode == 0)
                out[(size_t)b * 512 + j] = hn;
        }
        __syncthreads();
        if (tid == 0) flag_arrive(cta, (unsigned)(2 * lt + 2));
    }

    // ---- exit: last CTA of each group resets the group's flags ----
    __syncthreads();
    if (tid == 0) {
        unsigned a = atomicAdd(&g_cnt_exit[grp], 1u);
        if (a == 31) {
            g_cnt_exit[grp] = 0;
            for (int i = 0; i < 32; ++i) g_flags[grp * 32 + i] = 0;
            __threadfence();
        }
    }
}

// =============================================================================
// Launch: GEMM(c) overlapped with recurrence(c-1) via forked side stream.
// Dependencies: R(c) waits G(c) done; G(c+2) forks after R(c) (last reader of
// its target buffer). All side-stream work joins back via the evD waits.
// =============================================================================
extern "C" void kernel_launch(void* const* d_in, const int* in_sizes, int n_in,
                              void* d_out, int out_size) {
    const float* x  = (const float*)d_in[0];
    const float* Wr = (const float*)d_in[1];
    const float* br = (const float*)d_in[2];
    const float* Wz = (const float*)d_in[3];
    const float* bz = (const float*)d_in[4];
    const float* Wg = (const float*)d_in[5];
    const float* bg = (const float*)d_in[6];
    float* out = (float*)d_out;

    const long long TBH = (long long)T_STEPS * BATCH * DHID;   // 67,108,864
    int mode;
    if ((long long)out_size >= TBH + (long long)BATCH * DHID) mode = 2; // outs + h_final
    else if ((long long)out_size >= TBH)                      mode = 1; // outs only
    else                                                      mode = 0; // h_final only

    cudaFuncSetAttribute(gru_rec_kernel,
                         cudaFuncAttributeMaxDynamicSharedMemorySize,
                         REC_SMEM_BYTES);

    // side stream + events (created fresh each call; tiny host-side leak only,
    // no device memory, identical captured work every call)
    cudaStream_t s2;
    cudaStreamCreateWithFlags(&s2, cudaStreamNonBlocking);
    cudaEvent_t evF;
    cudaEventCreateWithFlags(&evF, cudaEventDisableTiming);
    cudaEvent_t evD[NCHUNK];
    for (int i = 0; i < NCHUNK; ++i)
        cudaEventCreateWithFlags(&evD[i], cudaEventDisableTiming);

    const size_t xstride = (size_t)CHUNK * BATCH * 512;
    dim3 g1(12, CHUNK * BATCH / 128);    // 12 N-tiles x 64 M-tiles

    init_h_kernel<<<DHID * BATCH / 256, 256>>>();

    // G0 on main stream
    gemm_xpre_kernel<<<g1, 256>>>(x, Wr, Wz, Wg, br, bz, bg, 0);

    // fork G1 on side stream (overlaps R0)
    cudaEventRecord(evF, 0);
    cudaStreamWaitEvent(s2, evF, 0);
    gemm_xpre_kernel<<<g1, 256, 0, s2>>>(x + xstride, Wr, Wz, Wg, br, bz, bg, 1);
    cudaEventRecord(evD[1], s2);

    for (int c = 0; c < NCHUNK; ++c) {
        if (c >= 1) cudaStreamWaitEvent(0, evD[c], 0);     // G(c) finished
        gru_rec_kernel<<<GRID_G, REC_THREADS, REC_SMEM_BYTES>>>(
            Wr, Wz, Wg, out, mode, c * CHUNK, c & 1);
        const int n = c + 2;
        if (n < NCHUNK) {                                  // buffer n&1 free after R(c)
            cudaEventRecord(evF, 0);
            cudaStreamWaitEvent(s2, evF, 0);
            gemm_xpre_kernel<<<g1, 256, 0, s2>>>(
                x + (size_t)n * xstride, Wr, Wz, Wg, br, bz, bg, n & 1);
            cudaEventRecord(evD[n], s2);
        }
    }
}